// round 15
// baseline (speedup 1.0000x reference)
#include <cuda_runtime.h>
#include <cstdint>

#define NUM_BINS 32
#define MAXK     4
#define MAXU     100352
#define NMAXV    (2*MAXU)
#define OBASE    (2*MAXU)
#define SPITCH   (4*MAXU + 16)
#define DUMPCOL  (4*MAXU)
#define XSP      129                  // u64 pitch of staged x rows
#define XS_BYTES (64 * XSP * 8)

typedef unsigned long long u64;

__device__ int   g_cnt[MAXU];
__device__ int4  g_list[MAXU];                   // packed (voxel<<5 | bin)
__device__ int   g_slot[NMAXV];                  // voxel -> column in g_xS
__device__ __align__(16) float g_xS[(size_t)64 * SPITCH];  // [c][col]
__device__ float g_xemp[64];                     // MLP(0) vector

// ---------------- packed f32x2 helpers -------------------------------------
__device__ __forceinline__ u64 pk2(float lo, float hi) {
    u64 r; asm("mov.b64 %0,{%1,%2};" : "=l"(r) : "f"(lo), "f"(hi)); return r;
}
__device__ __forceinline__ u64 dup2(float v) { return pk2(v, v); }
__device__ __forceinline__ void fma2(u64 &d, u64 a, u64 b) {
    asm("fma.rn.f32x2 %0,%1,%2,%0;" : "+l"(d) : "l"(a), "l"(b));
}
__device__ __forceinline__ float2 unpk(u64 v) {
    float2 r; asm("mov.b64 {%0,%1},%2;" : "=f"(r.x), "=f"(r.y) : "l"(v)); return r;
}
union F4U { float4 f; u64 u[2]; };

__device__ __forceinline__ float sigm(float x) {
    return __fdividef(1.f, 1.f + __expf(-x));
}

// ---------------------------------------------------------------- scatter ---
__global__ void scatter_kernel(const int* __restrict__ unq_inv,
                               const int* __restrict__ coords, int N) {
    int i = blockIdx.x * blockDim.x + threadIdx.x;
    if (i >= N) return;
    int p = unq_inv[i];
    int b = coords[4 * i + 1];
    int k = atomicAdd(&g_cnt[p], 1);
    int col;
    if (k < 2)          col = 2 * p + k;
    else if (k < MAXK)  col = OBASE + 2 * p + (k - 2);
    else                col = DUMPCOL;
    g_slot[i] = col;
    if (k < MAXK) ((int*)g_list)[p * 4 + k] = (i << 5) | (b & 31);
}

// ------------------------------------------------------------------- mask ---
__global__ void mask_kernel(const int* __restrict__ cnt, float* __restrict__ out,
                            long long base, int n) {
    int i = blockIdx.x * blockDim.x + threadIdx.x;
    if (i < n) out[base + i] = (cnt[i] >= 2) ? 1.0f : 0.0f;
}

// ------------------------------------------------------------------- xemp ---
__global__ void xemp_kernel(const float* __restrict__ b1,
                            const float* __restrict__ W2,
                            const float* __restrict__ b2) {
    int c = threadIdx.x;   // 64 threads
    float acc = b2[c];
#pragma unroll
    for (int j = 0; j < 32; j++)
        acc = fmaf(fmaxf(b1[j], 0.f), W2[j * 64 + c], acc);
    g_xemp[c] = acc;
}

// ---------------------------------------------------- kernel A: MLP (tiled) --
__global__ __launch_bounds__(256)
void mlp2_kernel(const float* __restrict__ vf,
                 const float* __restrict__ W1, const float* __restrict__ b1,
                 const float* __restrict__ W2, const float* __restrict__ b2,
                 int N) {
    __shared__ __align__(16) float W1s[5][32];
    __shared__ __align__(16) float b1s[32];
    __shared__ __align__(16) float W2s[32][64];
    __shared__ __align__(16) float b2s[64];
    __shared__ __align__(16) float h_sh[32][68];
    __shared__ __align__(16) float x_sh[64][65];
    __shared__ int col_sh[64];

    const int tid  = threadIdx.x;
    const int cp   = tid & 31;
    const int slot = tid >> 5;
    const int v0   = blockIdx.x * 64;

    for (int i = tid; i < 160; i += 256) W1s[i / 32][i % 32] = W1[i];
    if (tid < 32) b1s[tid] = b1[tid];
    for (int i = tid; i < 2048; i += 256) W2s[i >> 6][i & 63] = W2[i];
    if (tid < 64) b2s[tid] = b2[tid];
    if (tid >= 64 && tid < 128) {
        int v = tid - 64;
        col_sh[v] = (v0 + v < N) ? g_slot[v0 + v] : DUMPCOL;
    }
    __syncthreads();

    // ---- phase A: hidden ----
    {
        int v = tid & 63, qr = tid >> 6;
        int gv = v0 + v;
        float f[5];
        bool ok = gv < N;
#pragma unroll
        for (int i = 0; i < 5; i++) f[i] = ok ? vf[(size_t)gv * 5 + i] : 0.f;
        u64 acc[4];
#pragma unroll
        for (int t = 0; t < 4; t++) acc[t] = *(const u64*)&b1s[qr * 8 + 2 * t];
#pragma unroll
        for (int i = 0; i < 5; i++) {
            u64 fd = dup2(f[i]);
#pragma unroll
            for (int t = 0; t < 4; t++)
                fma2(acc[t], fd, *(const u64*)&W1s[i][qr * 8 + 2 * t]);
        }
#pragma unroll
        for (int t = 0; t < 4; t++) {
            float2 h = unpk(acc[t]);
            h_sh[qr * 8 + 2 * t][v]     = fmaxf(h.x, 0.f);
            h_sh[qr * 8 + 2 * t + 1][v] = fmaxf(h.y, 0.f);
        }
    }
    __syncthreads();

    // ---- phase B: layer 2 ----
    {
        const int vb = slot * 8;
        float2 b2p = *(const float2*)&b2s[2 * cp];
        u64 accA[4], accB[4];
#pragma unroll
        for (int t = 0; t < 4; t++) { accA[t] = dup2(b2p.x); accB[t] = dup2(b2p.y); }
#pragma unroll 4
        for (int j = 0; j < 32; j++) {
            F4U A, B;
            A.f = *(const float4*)&h_sh[j][vb];
            B.f = *(const float4*)&h_sh[j][vb + 4];
            float2 w = *(const float2*)&W2s[j][2 * cp];
            u64 d0 = dup2(w.x), d1 = dup2(w.y);
            fma2(accA[0], A.u[0], d0); fma2(accA[1], A.u[1], d0);
            fma2(accA[2], B.u[0], d0); fma2(accA[3], B.u[1], d0);
            fma2(accB[0], A.u[0], d1); fma2(accB[1], A.u[1], d1);
            fma2(accB[2], B.u[0], d1); fma2(accB[3], B.u[1], d1);
        }
#pragma unroll
        for (int t = 0; t < 4; t++) {
            float2 a = unpk(accA[t]);
            float2 b = unpk(accB[t]);
            x_sh[vb + 2 * t][2 * cp]         = a.x;
            x_sh[vb + 2 * t + 1][2 * cp]     = a.y;
            x_sh[vb + 2 * t][2 * cp + 1]     = b.x;
            x_sh[vb + 2 * t + 1][2 * cp + 1] = b.y;
        }
    }
    __syncthreads();

    // ---- writeout through slot map (coalesced when slots are identity) ----
    for (int idx = tid; idx < 64 * 64; idx += 256) {
        int c = idx >> 6, v = idx & 63;
        if (v0 + v < N) g_xS[(size_t)c * SPITCH + col_sh[v]] = x_sh[v][c];
    }
}

// -------------------------------------------------- kernel B: attention -----
// thread = pillar; block window of x (k<2 slots) staged in dynamic smem ->
// all hot x loads are conflict-free LDS.64. k>=2 overflow via gmem columns.
__global__ __launch_bounds__(128)
void pillar8_kernel(const int* __restrict__ unq_cnt,
                    const float* __restrict__ Wc1, const float* __restrict__ bc1,
                    const float* __restrict__ Wc2, const float* __restrict__ bc2,
                    const float* __restrict__ Wsp, const float* __restrict__ bsp,
                    float* __restrict__ out, int U) {
    extern __shared__ __align__(16) u64 xs[];       // [64][XSP] u64
    __shared__ __align__(16) float Wc1s[64 * 16];   // [c][j]
    __shared__ __align__(16) u64   Wc2P[32 * 16];   // [q][j] packed ch-pairs
    __shared__ __align__(16) float xemps[64];
    __shared__ __align__(16) u64   xem2[32];        // packed xemp pairs
    __shared__ float bc1s[16];
    __shared__ __align__(16) u64   bc22p[32];       // 2*bc2 packed pairs
    __shared__ __align__(16) u64   Amx[32];         // conv bg coeffs per bin
    __shared__ __align__(16) u64   wmx[8];          // packed (wm[t], wx[t])
    __shared__ __align__(16) u64   oh[8][131];      // quarter-output staging

    const int tid = threadIdx.x;
    const int pbase = blockIdx.x * 128;

    for (int i = tid; i < 1024; i += 128) Wc1s[i] = Wc1[i];
    for (int i = tid; i < 512; i += 128) {
        int q = i >> 4, j = i & 15;
        Wc2P[q * 16 + j] = pk2(Wc2[j * 64 + 2 * q], Wc2[j * 64 + 2 * q + 1]);
    }
    if (tid < 64) xemps[tid] = g_xemp[tid];
    if (tid < 32) {
        xem2[tid]  = pk2(g_xemp[2 * tid], g_xemp[2 * tid + 1]);
        bc22p[tid] = pk2(2.f * bc2[2 * tid], 2.f * bc2[2 * tid + 1]);
        float am = 0.f, ax = 0.f;
#pragma unroll
        for (int t = 0; t < 7; t++) {
            int i2 = tid + t - 3;
            if (i2 >= 0 && i2 < 32) { am += Wsp[t]; ax += Wsp[7 + t]; }
        }
        Amx[tid] = pk2(am, ax);
    }
    if (tid < 16) bc1s[tid] = bc1[tid];
    if (tid < 7)  wmx[tid] = pk2(Wsp[tid], Wsp[7 + tid]);

    // ---- stage this block's x window: columns [2*pbase, 2*pbase+256) ------
    {
        const size_t wbase = (size_t)2 * pbase;
        for (int idx = tid; idx < 64 * 128; idx += 128) {
            int c = idx >> 7, t = idx & 127;
            xs[c * XSP + t] = *(const u64*)&g_xS[(size_t)c * SPITCH + wbase + 2 * t];
        }
    }
    __syncthreads();

    const float bspv = bsp[0];
    const float NEG = __int_as_float(0xff800000);
    const int p = pbase + tid;
    const bool active = p < U;

    int K = 0;
    int4 e = make_int4(0, 0, 0, 0);
    if (active) {
        K = unq_cnt[p];
        K = (K < 0) ? 0 : ((K > MAXK) ? MAXK : K);
        e = g_list[p];
    }
    int bs_[4] = { e.x & 31, e.y & 31, e.z & 31, e.w & 31 };
#pragma unroll
    for (int k = 0; k < 4; k++) if (k >= K) bs_[k] = -1000;
    const float fK = (float)(NUM_BINS - K);

    // gmem base for overflow voxels (k=2,3), row-relative columns 0/1
    const float* xg = g_xS + OBASE + (size_t)2 * p;

    // ---- phase 1: avg/max per channel -> catt hidden partials -------------
    u64 ap[8], aq[8];
#pragma unroll
    for (int j = 0; j < 8; j++) { ap[j] = 0ull; aq[j] = 0ull; }
    {
        const u64* xr = xs + tid;
        const float* xo = xg;
#pragma unroll 4
        for (int c = 0; c < 64; c++) {
            float2 v = unpk(*xr);
            float xe = xemps[c];
            float s = 0.f, mx = xe;
            if (K > 0) { s += v.x; mx = fmaxf(mx, v.x); }
            if (K > 1) { s += v.y; mx = fmaxf(mx, v.y); }
            if (K > 2) {
                float t2 = xo[0]; s += t2; mx = fmaxf(mx, t2);
                if (K > 3) { float t3 = xo[1]; s += t3; mx = fmaxf(mx, t3); }
            }
            float av = (s + fK * xe) * 0.03125f;
            u64 ad = dup2(av), md = dup2(mx);
            const ulonglong2* wr = (const ulonglong2*)&Wc1s[c * 16];
#pragma unroll
            for (int h = 0; h < 4; h++) {
                ulonglong2 w = wr[h];
                fma2(ap[2 * h],     ad, w.x);
                fma2(ap[2 * h + 1], ad, w.y);
                fma2(aq[2 * h],     md, w.x);
                fma2(aq[2 * h + 1], md, w.y);
            }
            xr += XSP;
            xo += SPITCH;
        }
    }

    // ---- catt gate vector, packed dups -----------------------------------
    u64 gd[16];
#pragma unroll
    for (int jp = 0; jp < 8; jp++) {
        float2 pp = unpk(ap[jp]);
        float2 qq = unpk(aq[jp]);
        float g0 = fmaxf(pp.x + bc1s[2 * jp], 0.f)     + fmaxf(qq.x + bc1s[2 * jp], 0.f);
        float g1 = fmaxf(pp.y + bc1s[2 * jp + 1], 0.f) + fmaxf(qq.y + bc1s[2 * jp + 1], 0.f);
        gd[2 * jp]     = dup2(g0);
        gd[2 * jp + 1] = dup2(g1);
    }

    // ---- phase 2: channel attention + bin statistics ---------------------
    float ssum[4] = {0.f, 0.f, 0.f, 0.f};
    float smax4[4] = {NEG, NEG, NEG, NEG};
    float sesum = 0.f, semax = NEG;
    {
        const u64* xr = xs + tid;
        const float* xo = xg;
#pragma unroll 2
        for (int q = 0; q < 32; q++) {
            u64 acc = bc22p[q];
            const ulonglong2* w2 = (const ulonglong2*)&Wc2P[q * 16];
#pragma unroll
            for (int h = 0; h < 8; h++) {
                ulonglong2 w = w2[h];
                fma2(acc, gd[2 * h],     w.x);
                fma2(acc, gd[2 * h + 1], w.y);
            }
            float2 A = unpk(acc);
            float a0 = sigm(A.x), a1 = sigm(A.y);
            float2 xe = unpk(xem2[q]);
            float y0 = a0 * xe.x, y1 = a1 * xe.y;
            sesum += y0 + y1;
            semax = fmaxf(semax, fmaxf(y0, y1));
            float2 va = unpk(xr[0]);       // channel 2q:   (k0, k1)
            float2 vb = unpk(xr[XSP]);     // channel 2q+1: (k0, k1)
            if (K > 0) {
                float z0 = a0 * va.x, z1 = a1 * vb.x;
                ssum[0] += z0 + z1;
                smax4[0] = fmaxf(smax4[0], fmaxf(z0, z1));
            }
            if (K > 1) {
                float z0 = a0 * va.y, z1 = a1 * vb.y;
                ssum[1] += z0 + z1;
                smax4[1] = fmaxf(smax4[1], fmaxf(z0, z1));
            }
            if (K > 2) {
                float z0 = a0 * xo[0], z1 = a1 * xo[SPITCH];
                ssum[2] += z0 + z1;
                smax4[2] = fmaxf(smax4[2], fmaxf(z0, z1));
                if (K > 3) {
                    float w0 = a0 * xo[1], w1 = a1 * xo[SPITCH + 1];
                    ssum[3] += w0 + w1;
                    smax4[3] = fmaxf(smax4[3], fmaxf(w0, w1));
                }
            }
            xr += 2 * XSP;
            xo += 2 * SPITCH;
        }
    }

    // ---- bin attention: bg + sparse corrections --------------------------
    const float se_m = sesum * (1.f / 64.f);
    const float se_x = semax;
    const u64 semx = pk2(se_m, se_x);
    u64 dk2[4];
#pragma unroll
    for (int k = 0; k < 4; k++)
        dk2[k] = pk2(ssum[k] * (1.f / 64.f) - se_m, smax4[k] - se_x);

    float argk[4] = {0.f, 0.f, 0.f, 0.f};
    float emax = NEG, emin = -NEG;
#pragma unroll
    for (int b = 0; b < 32; b++) {
        u64 a2 = pk2(bspv, 0.f);
        fma2(a2, semx, Amx[b]);
        bool occ = false;
        bool hit[4];
#pragma unroll
        for (int k = 0; k < 4; k++) {
            int d = bs_[k] - b;
            if ((unsigned)(d + 3) <= 6u) fma2(a2, dk2[k], wmx[d + 3]);
            hit[k] = (d == 0);
            occ |= hit[k];
        }
        float2 av = unpk(a2);
        float a = av.x + av.y;
#pragma unroll
        for (int k = 0; k < 4; k++) argk[k] = hit[k] ? a : argk[k];
        emax = occ ? emax : fmaxf(emax, a);
        emin = occ ? emin : fminf(emin, a);
    }
    float sigk[4];
#pragma unroll
    for (int k = 0; k < 4; k++) sigk[k] = sigm(argk[k]);
    const float sigeP = sigm(emax);    // y_empty >= 0
    const float sigeN = sigm(emin);    // y_empty <  0

    // ---- phase 3: final max over bins, 4 staged quarters -----------------
#pragma unroll
    for (int quarter = 0; quarter < 4; quarter++) {
        {
            const u64* xr = xs + (quarter * 16) * XSP + tid;
            const float* xo = xg + (size_t)(quarter * 16) * SPITCH;
#pragma unroll 2
            for (int qq = 0; qq < 8; qq++) {
                int q = quarter * 8 + qq;
                u64 acc = bc22p[q];
                const ulonglong2* w2 = (const ulonglong2*)&Wc2P[q * 16];
#pragma unroll
                for (int h = 0; h < 8; h++) {
                    ulonglong2 w = w2[h];
                    fma2(acc, gd[2 * h],     w.x);
                    fma2(acc, gd[2 * h + 1], w.y);
                }
                float2 A = unpk(acc);
                float a0 = sigm(A.x), a1 = sigm(A.y);
                float2 xe = unpk(xem2[q]);
                float M0 = xe.x * ((xe.x >= 0.f) ? sigeP : sigeN);
                float M1 = xe.y * ((xe.y >= 0.f) ? sigeP : sigeN);
                float2 va = unpk(xr[0]);
                float2 vb = unpk(xr[XSP]);
                if (K > 0) {
                    M0 = fmaxf(M0, va.x * sigk[0]);
                    M1 = fmaxf(M1, vb.x * sigk[0]);
                }
                if (K > 1) {
                    M0 = fmaxf(M0, va.y * sigk[1]);
                    M1 = fmaxf(M1, vb.y * sigk[1]);
                }
                if (K > 2) {
                    M0 = fmaxf(M0, xo[0] * sigk[2]);
                    M1 = fmaxf(M1, xo[SPITCH] * sigk[2]);
                    if (K > 3) {
                        M0 = fmaxf(M0, xo[1] * sigk[3]);
                        M1 = fmaxf(M1, xo[SPITCH + 1] * sigk[3]);
                    }
                }
                oh[qq][tid] = pk2(a0 * M0, a1 * M1);
                xr += 2 * XSP;
                xo += 2 * SPITCH;
            }
        }
        __syncthreads();
        for (int idx = tid; idx < 128 * 8; idx += 128) {
            int pl = idx >> 3, qq = idx & 7;
            int pg = pbase + pl;
            if (pg < U)
                *(u64*)(out + (size_t)pg * 64 + quarter * 16 + 2 * qq) = oh[qq][pl];
        }
        __syncthreads();
    }
}

// ------------------------------------------------------------------ launch --
extern "C" void kernel_launch(void* const* d_in, const int* in_sizes, int n_in,
                              void* d_out, int out_size) {
    const float* vf      = (const float*)d_in[0];
    const int*   coords  = (const int*)  d_in[1];
    const int*   unq_inv = (const int*)  d_in[3];
    const int*   unq_cnt = (const int*)  d_in[4];
    const float* W1  = (const float*)d_in[5];
    const float* b1  = (const float*)d_in[6];
    const float* W2  = (const float*)d_in[7];
    const float* b2  = (const float*)d_in[8];
    const float* Wc1 = (const float*)d_in[9];
    const float* bc1 = (const float*)d_in[10];
    const float* Wc2 = (const float*)d_in[11];
    const float* bc2 = (const float*)d_in[12];
    const float* Wsp = (const float*)d_in[13];
    const float* bsp = (const float*)d_in[14];
    float* out = (float*)d_out;

    int N = in_sizes[0] / 5;
    if (N > NMAXV) N = NMAXV;
    int U = in_sizes[2];
    if (U > MAXU) U = MAXU;

    static bool attr_set = false;
    if (!attr_set) {
        cudaFuncSetAttribute(pillar8_kernel,
                             cudaFuncAttributeMaxDynamicSharedMemorySize, XS_BYTES);
        attr_set = true;
    }

    void* cnt_ptr = nullptr;
    cudaGetSymbolAddress(&cnt_ptr, g_cnt);
    cudaMemsetAsync(cnt_ptr, 0, (size_t)U * sizeof(int));

    scatter_kernel<<<(N + 255) / 256, 256>>>(unq_inv, coords, N);
    xemp_kernel<<<1, 64>>>(b1, W2, b2);
    mlp2_kernel<<<(N + 63) / 64, 256>>>(vf, W1, b1, W2, b2, N);
    pillar8_kernel<<<(U + 127) / 128, 128, XS_BYTES>>>(unq_cnt, Wc1, bc1, Wc2, bc2,
                                                       Wsp, bsp, out, U);

    long long feat = (long long)U * 64;
    if ((long long)out_size > feat) {
        long long extra = (long long)out_size - feat;
        int n = (extra > U) ? U : (int)extra;
        mask_kernel<<<(n + 255) / 256, 256>>>(unq_cnt, out, feat, n);
    }
}

// round 17
// speedup vs baseline: 1.2359x; 1.2359x over previous
#include <cuda_runtime.h>
#include <cstdint>

#define NUM_BINS 32
#define MAXK     4
#define MAXU     100352
#define NMAXV    (2*MAXU)
#define OBASE    (2*MAXU)
#define SPITCH   (4*MAXU + 16)
#define SPH2     (SPITCH/2)           // u64 pitch of g_xS rows
#define DUMPCOL  (4*MAXU)

typedef unsigned long long u64;

__device__ int   g_cnt[MAXU];
__device__ int4  g_list[MAXU];                   // packed (voxel<<5 | bin)
__device__ int   g_slot[NMAXV];                  // voxel -> column in g_xS
__device__ __align__(16) float g_xS[(size_t)64 * SPITCH];  // [c][col]
__device__ float g_xemp[64];                     // MLP(0) vector

// ---------------- packed f32x2 helpers -------------------------------------
__device__ __forceinline__ u64 pk2(float lo, float hi) {
    u64 r; asm("mov.b64 %0,{%1,%2};" : "=l"(r) : "f"(lo), "f"(hi)); return r;
}
__device__ __forceinline__ u64 dup2(float v) { return pk2(v, v); }
__device__ __forceinline__ void fma2(u64 &d, u64 a, u64 b) {
    asm("fma.rn.f32x2 %0,%1,%2,%0;" : "+l"(d) : "l"(a), "l"(b));
}
__device__ __forceinline__ float2 unpk(u64 v) {
    float2 r; asm("mov.b64 {%0,%1},%2;" : "=f"(r.x), "=f"(r.y) : "l"(v)); return r;
}
union F4U { float4 f; u64 u[2]; };

__device__ __forceinline__ float sigm(float x) {
    return __fdividef(1.f, 1.f + __expf(-x));
}

// ---------------------------------------------------------------- scatter ---
__global__ void scatter_kernel(const int* __restrict__ unq_inv,
                               const int* __restrict__ coords, int N) {
    int i = blockIdx.x * blockDim.x + threadIdx.x;
    if (i >= N) return;
    int p = unq_inv[i];
    int b = coords[4 * i + 1];
    int k = atomicAdd(&g_cnt[p], 1);
    int col;
    if (k < 2)          col = 2 * p + k;
    else if (k < MAXK)  col = OBASE + 2 * p + (k - 2);
    else                col = DUMPCOL;
    g_slot[i] = col;
    if (k < MAXK) ((int*)g_list)[p * 4 + k] = (i << 5) | (b & 31);
}

// ------------------------------------------------------------------- mask ---
__global__ void mask_kernel(const int* __restrict__ cnt, float* __restrict__ out,
                            long long base, int n) {
    int i = blockIdx.x * blockDim.x + threadIdx.x;
    if (i < n) out[base + i] = (cnt[i] >= 2) ? 1.0f : 0.0f;
}

// ------------------------------------------------------------------- xemp ---
__global__ void xemp_kernel(const float* __restrict__ b1,
                            const float* __restrict__ W2,
                            const float* __restrict__ b2) {
    int c = threadIdx.x;   // 64 threads
    float acc = b2[c];
#pragma unroll
    for (int j = 0; j < 32; j++)
        acc = fmaf(fmaxf(b1[j], 0.f), W2[j * 64 + c], acc);
    g_xemp[c] = acc;
}

// ---------------------------------------------------- kernel A: MLP (tiled) --
__global__ __launch_bounds__(256)
void mlp2_kernel(const float* __restrict__ vf,
                 const float* __restrict__ W1, const float* __restrict__ b1,
                 const float* __restrict__ W2, const float* __restrict__ b2,
                 int N) {
    __shared__ __align__(16) float W1s[5][32];
    __shared__ __align__(16) float b1s[32];
    __shared__ __align__(16) float W2s[32][64];
    __shared__ __align__(16) float b2s[64];
    __shared__ __align__(16) float h_sh[32][68];
    __shared__ __align__(16) float x_sh[64][65];
    __shared__ int col_sh[64];

    const int tid  = threadIdx.x;
    const int cp   = tid & 31;
    const int slot = tid >> 5;
    const int v0   = blockIdx.x * 64;

    for (int i = tid; i < 160; i += 256) W1s[i / 32][i % 32] = W1[i];
    if (tid < 32) b1s[tid] = b1[tid];
    for (int i = tid; i < 2048; i += 256) W2s[i >> 6][i & 63] = W2[i];
    if (tid < 64) b2s[tid] = b2[tid];
    if (tid >= 64 && tid < 128) {
        int v = tid - 64;
        col_sh[v] = (v0 + v < N) ? g_slot[v0 + v] : DUMPCOL;
    }
    __syncthreads();

    // ---- phase A: hidden ----
    {
        int v = tid & 63, qr = tid >> 6;
        int gv = v0 + v;
        float f[5];
        bool ok = gv < N;
#pragma unroll
        for (int i = 0; i < 5; i++) f[i] = ok ? vf[(size_t)gv * 5 + i] : 0.f;
        u64 acc[4];
#pragma unroll
        for (int t = 0; t < 4; t++) acc[t] = *(const u64*)&b1s[qr * 8 + 2 * t];
#pragma unroll
        for (int i = 0; i < 5; i++) {
            u64 fd = dup2(f[i]);
#pragma unroll
            for (int t = 0; t < 4; t++)
                fma2(acc[t], fd, *(const u64*)&W1s[i][qr * 8 + 2 * t]);
        }
#pragma unroll
        for (int t = 0; t < 4; t++) {
            float2 h = unpk(acc[t]);
            h_sh[qr * 8 + 2 * t][v]     = fmaxf(h.x, 0.f);
            h_sh[qr * 8 + 2 * t + 1][v] = fmaxf(h.y, 0.f);
        }
    }
    __syncthreads();

    // ---- phase B: layer 2 ----
    {
        const int vb = slot * 8;
        float2 b2p = *(const float2*)&b2s[2 * cp];
        u64 accA[4], accB[4];
#pragma unroll
        for (int t = 0; t < 4; t++) { accA[t] = dup2(b2p.x); accB[t] = dup2(b2p.y); }
#pragma unroll 4
        for (int j = 0; j < 32; j++) {
            F4U A, B;
            A.f = *(const float4*)&h_sh[j][vb];
            B.f = *(const float4*)&h_sh[j][vb + 4];
            float2 w = *(const float2*)&W2s[j][2 * cp];
            u64 d0 = dup2(w.x), d1 = dup2(w.y);
            fma2(accA[0], A.u[0], d0); fma2(accA[1], A.u[1], d0);
            fma2(accA[2], B.u[0], d0); fma2(accA[3], B.u[1], d0);
            fma2(accB[0], A.u[0], d1); fma2(accB[1], A.u[1], d1);
            fma2(accB[2], B.u[0], d1); fma2(accB[3], B.u[1], d1);
        }
#pragma unroll
        for (int t = 0; t < 4; t++) {
            float2 a = unpk(accA[t]);
            float2 b = unpk(accB[t]);
            x_sh[vb + 2 * t][2 * cp]         = a.x;
            x_sh[vb + 2 * t + 1][2 * cp]     = a.y;
            x_sh[vb + 2 * t][2 * cp + 1]     = b.x;
            x_sh[vb + 2 * t + 1][2 * cp + 1] = b.y;
        }
    }
    __syncthreads();

    // ---- writeout through slot map (coalesced when slots are identity) ----
    for (int idx = tid; idx < 64 * 64; idx += 256) {
        int c = idx >> 6, v = idx & 63;
        if (v0 + v < N) g_xS[(size_t)c * SPITCH + col_sh[v]] = x_sh[v][c];
    }
}

// -------------------------------------------------- kernel B: attention -----
// thread = pillar. Slot-gathered x: each pillar's k<2 voxels are ONE aligned
// u64 at column p (u64-indexed) -> direct LDG.64, single code path, contiguous
// per-warp spans. k>=2 overflow in separate gmem region (guarded).
__global__ __launch_bounds__(128, 6)
void pillar9_kernel(const int* __restrict__ unq_cnt,
                    const float* __restrict__ Wc1, const float* __restrict__ bc1,
                    const float* __restrict__ Wc2, const float* __restrict__ bc2,
                    const float* __restrict__ Wsp, const float* __restrict__ bsp,
                    float* __restrict__ out, int U) {
    __shared__ __align__(16) float Wc1s[64 * 16];   // [c][j]
    __shared__ __align__(16) u64   Wc2P[32 * 16];   // [q][j] packed ch-pairs
    __shared__ __align__(16) float xemps[64];
    __shared__ __align__(16) u64   xem2[32];        // packed xemp pairs
    __shared__ float bc1s[16];
    __shared__ __align__(16) u64   bc22p[32];       // 2*bc2 packed pairs
    __shared__ __align__(16) u64   Amx[32];         // conv bg coeffs per bin
    __shared__ __align__(16) u64   wmx[8];          // packed (wm[t], wx[t])
    __shared__ __align__(16) u64   oh[8][131];      // quarter-output staging

    const int tid = threadIdx.x;
    const int pbase = blockIdx.x * 128;

    for (int i = tid; i < 1024; i += 128) Wc1s[i] = Wc1[i];
    for (int i = tid; i < 512; i += 128) {
        int q = i >> 4, j = i & 15;
        Wc2P[q * 16 + j] = pk2(Wc2[j * 64 + 2 * q], Wc2[j * 64 + 2 * q + 1]);
    }
    if (tid < 64) xemps[tid] = g_xemp[tid];
    if (tid < 32) {
        xem2[tid]  = pk2(g_xemp[2 * tid], g_xemp[2 * tid + 1]);
        bc22p[tid] = pk2(2.f * bc2[2 * tid], 2.f * bc2[2 * tid + 1]);
        float am = 0.f, ax = 0.f;
#pragma unroll
        for (int t = 0; t < 7; t++) {
            int i2 = tid + t - 3;
            if (i2 >= 0 && i2 < 32) { am += Wsp[t]; ax += Wsp[7 + t]; }
        }
        Amx[tid] = pk2(am, ax);
    }
    if (tid < 16) bc1s[tid] = bc1[tid];
    if (tid < 7)  wmx[tid] = pk2(Wsp[tid], Wsp[7 + tid]);
    __syncthreads();

    const float bspv = bsp[0];
    const float NEG = __int_as_float(0xff800000);
    const int p = pbase + tid;
    const bool active = p < U;

    int K = 0;
    int4 e = make_int4(0, 0, 0, 0);
    if (active) {
        K = unq_cnt[p];
        K = (K < 0) ? 0 : ((K > MAXK) ? MAXK : K);
        e = g_list[p];
    }
    int bs_[4] = { e.x & 31, e.y & 31, e.z & 31, e.w & 31 };
#pragma unroll
    for (int k = 0; k < 4; k++) if (k >= K) bs_[k] = -1000;
    const float fK = (float)(NUM_BINS - K);

    // u64 base for the k<2 voxel pair of this pillar; float base for overflow
    const u64* xq = (const u64*)g_xS + (size_t)p;       // stride SPH2 per channel
    const float* xg = g_xS + OBASE + (size_t)2 * p;     // stride SPITCH

    // ---- phase 1: avg/max per channel -> catt hidden partials -------------
    u64 ap[8], aq[8];
#pragma unroll
    for (int j = 0; j < 8; j++) { ap[j] = 0ull; aq[j] = 0ull; }
    {
        const u64* xr = xq;
        const float* xo = xg;
#pragma unroll 4
        for (int c = 0; c < 64; c++) {
            float2 v = unpk(*xr);
            float xe = xemps[c];
            float s = 0.f, mx = xe;
            if (K > 0) { s += v.x; mx = fmaxf(mx, v.x); }
            if (K > 1) { s += v.y; mx = fmaxf(mx, v.y); }
            if (K > 2) {
                float t2 = xo[0]; s += t2; mx = fmaxf(mx, t2);
                if (K > 3) { float t3 = xo[1]; s += t3; mx = fmaxf(mx, t3); }
            }
            float av = (s + fK * xe) * 0.03125f;
            u64 ad = dup2(av), md = dup2(mx);
            const ulonglong2* wr = (const ulonglong2*)&Wc1s[c * 16];
#pragma unroll
            for (int h = 0; h < 4; h++) {
                ulonglong2 w = wr[h];
                fma2(ap[2 * h],     ad, w.x);
                fma2(ap[2 * h + 1], ad, w.y);
                fma2(aq[2 * h],     md, w.x);
                fma2(aq[2 * h + 1], md, w.y);
            }
            xr += SPH2;
            xo += SPITCH;
        }
    }

    // ---- catt gate vector, packed dups -----------------------------------
    u64 gd[16];
#pragma unroll
    for (int jp = 0; jp < 8; jp++) {
        float2 pp = unpk(ap[jp]);
        float2 qq = unpk(aq[jp]);
        float g0 = fmaxf(pp.x + bc1s[2 * jp], 0.f)     + fmaxf(qq.x + bc1s[2 * jp], 0.f);
        float g1 = fmaxf(pp.y + bc1s[2 * jp + 1], 0.f) + fmaxf(qq.y + bc1s[2 * jp + 1], 0.f);
        gd[2 * jp]     = dup2(g0);
        gd[2 * jp + 1] = dup2(g1);
    }

    // ---- phase 2: channel attention + bin statistics ---------------------
    float ssum[4] = {0.f, 0.f, 0.f, 0.f};
    float smax4[4] = {NEG, NEG, NEG, NEG};
    float sesum = 0.f, semax = NEG;
    {
        const u64* xr = xq;
        const float* xo = xg;
#pragma unroll 2
        for (int q = 0; q < 32; q++) {
            u64 acc = bc22p[q];
            const ulonglong2* w2 = (const ulonglong2*)&Wc2P[q * 16];
#pragma unroll
            for (int h = 0; h < 8; h++) {
                ulonglong2 w = w2[h];
                fma2(acc, gd[2 * h],     w.x);
                fma2(acc, gd[2 * h + 1], w.y);
            }
            float2 A = unpk(acc);
            float a0 = sigm(A.x), a1 = sigm(A.y);
            float2 xe = unpk(xem2[q]);
            float y0 = a0 * xe.x, y1 = a1 * xe.y;
            sesum += y0 + y1;
            semax = fmaxf(semax, fmaxf(y0, y1));
            float2 va = unpk(xr[0]);       // channel 2q:   (k0, k1)
            float2 vb = unpk(xr[SPH2]);    // channel 2q+1: (k0, k1)
            if (K > 0) {
                float z0 = a0 * va.x, z1 = a1 * vb.x;
                ssum[0] += z0 + z1;
                smax4[0] = fmaxf(smax4[0], fmaxf(z0, z1));
            }
            if (K > 1) {
                float z0 = a0 * va.y, z1 = a1 * vb.y;
                ssum[1] += z0 + z1;
                smax4[1] = fmaxf(smax4[1], fmaxf(z0, z1));
            }
            if (K > 2) {
                float z0 = a0 * xo[0], z1 = a1 * xo[SPITCH];
                ssum[2] += z0 + z1;
                smax4[2] = fmaxf(smax4[2], fmaxf(z0, z1));
                if (K > 3) {
                    float w0 = a0 * xo[1], w1 = a1 * xo[SPITCH + 1];
                    ssum[3] += w0 + w1;
                    smax4[3] = fmaxf(smax4[3], fmaxf(w0, w1));
                }
            }
            xr += 2 * SPH2;
            xo += 2 * SPITCH;
        }
    }

    // ---- bin attention: bg + sparse corrections --------------------------
    const float se_m = sesum * (1.f / 64.f);
    const float se_x = semax;
    const u64 semx = pk2(se_m, se_x);
    u64 dk2[4];
#pragma unroll
    for (int k = 0; k < 4; k++)
        dk2[k] = pk2(ssum[k] * (1.f / 64.f) - se_m, smax4[k] - se_x);

    float argk[4] = {0.f, 0.f, 0.f, 0.f};
    float emax = NEG, emin = -NEG;
#pragma unroll
    for (int b = 0; b < 32; b++) {
        u64 a2 = pk2(bspv, 0.f);
        fma2(a2, semx, Amx[b]);
        bool occ = false;
        bool hit[4];
#pragma unroll
        for (int k = 0; k < 4; k++) {
            int d = bs_[k] - b;
            if ((unsigned)(d + 3) <= 6u) fma2(a2, dk2[k], wmx[d + 3]);
            hit[k] = (d == 0);
            occ |= hit[k];
        }
        float2 av = unpk(a2);
        float a = av.x + av.y;
#pragma unroll
        for (int k = 0; k < 4; k++) argk[k] = hit[k] ? a : argk[k];
        emax = occ ? emax : fmaxf(emax, a);
        emin = occ ? emin : fminf(emin, a);
    }
    float sigk[4];
#pragma unroll
    for (int k = 0; k < 4; k++) sigk[k] = sigm(argk[k]);
    const float sigeP = sigm(emax);    // y_empty >= 0
    const float sigeN = sigm(emin);    // y_empty <  0

    // ---- phase 3: final max over bins, 4 staged quarters -----------------
#pragma unroll
    for (int quarter = 0; quarter < 4; quarter++) {
        {
            const u64* xr = xq + (size_t)(quarter * 16) * SPH2;
            const float* xo = xg + (size_t)(quarter * 16) * SPITCH;
#pragma unroll 2
            for (int qq = 0; qq < 8; qq++) {
                int q = quarter * 8 + qq;
                u64 acc = bc22p[q];
                const ulonglong2* w2 = (const ulonglong2*)&Wc2P[q * 16];
#pragma unroll
                for (int h = 0; h < 8; h++) {
                    ulonglong2 w = w2[h];
                    fma2(acc, gd[2 * h],     w.x);
                    fma2(acc, gd[2 * h + 1], w.y);
                }
                float2 A = unpk(acc);
                float a0 = sigm(A.x), a1 = sigm(A.y);
                float2 xe = unpk(xem2[q]);
                float M0 = xe.x * ((xe.x >= 0.f) ? sigeP : sigeN);
                float M1 = xe.y * ((xe.y >= 0.f) ? sigeP : sigeN);
                float2 va = unpk(xr[0]);
                float2 vb = unpk(xr[SPH2]);
                if (K > 0) {
                    M0 = fmaxf(M0, va.x * sigk[0]);
                    M1 = fmaxf(M1, vb.x * sigk[0]);
                }
                if (K > 1) {
                    M0 = fmaxf(M0, va.y * sigk[1]);
                    M1 = fmaxf(M1, vb.y * sigk[1]);
                }
                if (K > 2) {
                    M0 = fmaxf(M0, xo[0] * sigk[2]);
                    M1 = fmaxf(M1, xo[SPITCH] * sigk[2]);
                    if (K > 3) {
                        M0 = fmaxf(M0, xo[1] * sigk[3]);
                        M1 = fmaxf(M1, xo[SPITCH + 1] * sigk[3]);
                    }
                }
                oh[qq][tid] = pk2(a0 * M0, a1 * M1);
                xr += 2 * SPH2;
                xo += 2 * SPITCH;
            }
        }
        __syncthreads();
        for (int idx = tid; idx < 128 * 8; idx += 128) {
            int pl = idx >> 3, qq = idx & 7;
            int pg = pbase + pl;
            if (pg < U)
                *(u64*)(out + (size_t)pg * 64 + quarter * 16 + 2 * qq) = oh[qq][pl];
        }
        __syncthreads();
    }
}

// ------------------------------------------------------------------ launch --
extern "C" void kernel_launch(void* const* d_in, const int* in_sizes, int n_in,
                              void* d_out, int out_size) {
    const float* vf      = (const float*)d_in[0];
    const int*   coords  = (const int*)  d_in[1];
    const int*   unq_inv = (const int*)  d_in[3];
    const int*   unq_cnt = (const int*)  d_in[4];
    const float* W1  = (const float*)d_in[5];
    const float* b1  = (const float*)d_in[6];
    const float* W2  = (const float*)d_in[7];
    const float* b2  = (const float*)d_in[8];
    const float* Wc1 = (const float*)d_in[9];
    const float* bc1 = (const float*)d_in[10];
    const float* Wc2 = (const float*)d_in[11];
    const float* bc2 = (const float*)d_in[12];
    const float* Wsp = (const float*)d_in[13];
    const float* bsp = (const float*)d_in[14];
    float* out = (float*)d_out;

    int N = in_sizes[0] / 5;
    if (N > NMAXV) N = NMAXV;
    int U = in_sizes[2];
    if (U > MAXU) U = MAXU;

    void* cnt_ptr = nullptr;
    cudaGetSymbolAddress(&cnt_ptr, g_cnt);
    cudaMemsetAsync(cnt_ptr, 0, (size_t)U * sizeof(int));

    scatter_kernel<<<(N + 255) / 256, 256>>>(unq_inv, coords, N);
    xemp_kernel<<<1, 64>>>(b1, W2, b2);
    mlp2_kernel<<<(N + 63) / 64, 256>>>(vf, W1, b1, W2, b2, N);
    pillar9_kernel<<<(U + 127) / 128, 128>>>(unq_cnt, Wc1, bc1, Wc2, bc2,
                                             Wsp, bsp, out, U);

    long long feat = (long long)U * 64;
    if ((long long)out_size > feat) {
        long long extra = (long long)out_size - feat;
        int n = (extra > U) ? U : (int)extra;
        mask_kernel<<<(n + 255) / 256, 256>>>(unq_cnt, out, feat, n);
    }
}